// round 3
// baseline (speedup 1.0000x reference)
#include <cuda_runtime.h>

// ---------------------------------------------------------------------------
// HiLo attention, fp32.
// x: (4, 512, 64, 64)  -> per-batch this is exactly A^T (K=512 rows, M=4096
// cols, row-major) for a TN GEMM. All 5 GEMMs use one kernel.
// ---------------------------------------------------------------------------

#define NBATCH 4

// scratch layout (floats)
#define OFF_POOL  0L                  // pooledT (B,512,1024)      2,097,152
#define OFF_HQKV  2097152L            // hqkv    (B,4096,768)     12,582,912
#define OFF_LQ    14680064L           // lq      (B,4096,256)      4,194,304
#define OFF_LKV   18874368L           // lkv     (B,1024,512)      2,097,152
#define OFF_HOUT  20971520L           // houtT   (B,256,4096)      4,194,304
#define OFF_LOT   25165824L           // loT     (B,256,4096)      4,194,304
#define SCRATCH_FLOATS 29360128L

__device__ float g_scratch[SCRATCH_FLOATS];

// ---------------------------------------------------------------------------
// 2x2 mean pool:  pooledT[b][c][g] = mean of x[b][c] over window g
// ---------------------------------------------------------------------------
__global__ __launch_bounds__(256)
void pool_kernel(const float* __restrict__ x, float* __restrict__ pooledT) {
    long idx = (long)blockIdx.x * 256 + threadIdx.x;   // B*512*1024 = 2^21 total
    int g = (int)(idx & 1023);
    int c = (int)((idx >> 10) & 511);
    int b = (int)(idx >> 19);
    int gh = g >> 5, gw = g & 31;
    const float* p = x + ((long)(b * 512 + c) << 12) + (gh << 7) + (gw << 1);
    pooledT[idx] = 0.25f * (p[0] + p[1] + p[64] + p[65]);
}

// ---------------------------------------------------------------------------
// Generic batched TN SGEMM: C[b] = A[b]^T * Bw   (A stored K-major: K x lda)
// 128x128 tile, K-step 8, 256 threads, 8x8 microtile, register prefetch.
// TRANSC: write C column-major into d_out at channel offset coff (+ bias).
// Requires M%128==0, N%128==0, K%8==0 (all shapes here satisfy this).
// ---------------------------------------------------------------------------
template<int TRANSC, int BIAS>
__global__ __launch_bounds__(256)
void sgemm_tn(const float* __restrict__ A, long aBatch, int lda,
              const float* __restrict__ Bw, int ldb,
              float* __restrict__ C, long cBatch, int ldc, int coff,
              const float* __restrict__ bias, int K) {
    __shared__ float As[8][128];
    __shared__ float Bs[8][128];
    int tid = threadIdx.x;
    int bm = blockIdx.x, bn = blockIdx.y, b = blockIdx.z;
    const float* Ab = A + (long)b * aBatch + bm * 128;
    const float* Bb = Bw + bn * 128;
    int la_k = tid >> 5;             // 0..7
    int la_m = (tid & 31) << 2;      // 0..124
    int tx = tid & 15, ty = tid >> 4;

    float acc[8][8];
#pragma unroll
    for (int i = 0; i < 8; i++)
#pragma unroll
        for (int j = 0; j < 8; j++) acc[i][j] = 0.f;

    int KT = K >> 3;
    float4 ra = *(const float4*)(Ab + la_k * lda + la_m);
    float4 rb = *(const float4*)(Bb + la_k * ldb + la_m);

    for (int kt = 0; kt < KT; ++kt) {
        *(float4*)&As[la_k][la_m] = ra;
        *(float4*)&Bs[la_k][la_m] = rb;
        __syncthreads();
        if (kt + 1 < KT) {
            int k8 = (kt + 1) * 8 + la_k;
            ra = *(const float4*)(Ab + (long)k8 * lda + la_m);
            rb = *(const float4*)(Bb + (long)k8 * ldb + la_m);
        }
#pragma unroll
        for (int kk = 0; kk < 8; ++kk) {
            float a[8], bv[8];
            *(float4*)(a)     = *(float4*)&As[kk][ty << 2];
            *(float4*)(a + 4) = *(float4*)&As[kk][64 + (ty << 2)];
            *(float4*)(bv)     = *(float4*)&Bs[kk][tx << 2];
            *(float4*)(bv + 4) = *(float4*)&Bs[kk][64 + (tx << 2)];
#pragma unroll
            for (int i = 0; i < 8; i++)
#pragma unroll
                for (int j = 0; j < 8; j++)
                    acc[i][j] += a[i] * bv[j];
        }
        __syncthreads();
    }

    if (TRANSC) {
        float bs[8];
#pragma unroll
        for (int j = 0; j < 8; j++) {
            int n = bn * 128 + ((j < 4) ? (tx * 4 + j) : (64 + tx * 4 + j - 4));
            bs[j] = BIAS ? bias[n] : 0.f;
        }
#pragma unroll
        for (int i = 0; i < 8; i++) {
            int m = bm * 128 + ((i < 4) ? (ty * 4 + i) : (64 + ty * 4 + i - 4));
#pragma unroll
            for (int j = 0; j < 8; j++) {
                int n = bn * 128 + ((j < 4) ? (tx * 4 + j) : (64 + tx * 4 + j - 4));
                C[(long)b * cBatch + (long)(coff + n) * ldc + m] = acc[i][j] + bs[j];
            }
        }
    } else {
#pragma unroll
        for (int i = 0; i < 8; i++) {
            int m = bm * 128 + ((i < 4) ? (ty * 4 + i) : (64 + ty * 4 + i - 4));
            long cb = (long)b * cBatch + (long)m * ldc + bn * 128;
            float4 v0 = make_float4(acc[i][0], acc[i][1], acc[i][2], acc[i][3]);
            float4 v1 = make_float4(acc[i][4], acc[i][5], acc[i][6], acc[i][7]);
            *(float4*)&C[cb + (tx << 2)] = v0;
            *(float4*)&C[cb + 64 + (tx << 2)] = v1;
        }
    }
}

// ---------------------------------------------------------------------------
// Hi-fi windowed attention: one CTA (128 thr) per (b, window g).
// warp = head; 4 tokens x 4 heads x 64 dims. Output written channel-major
// (houtT: B x 256 x 4096) so h_proj can reuse the TN GEMM.
// ---------------------------------------------------------------------------
__global__ __launch_bounds__(128)
void hifi_attn(const float* __restrict__ hqkv, float* __restrict__ houtT) {
    __shared__ float sq[4][772];   // 4 tokens x 768 (+4 pad vs bank conflicts)
    int g = blockIdx.x, b = blockIdx.y;
    int gh = g >> 5, gw = g & 31;
    int tid = threadIdx.x;
    int t00 = (gh << 7) + (gw << 1);          // token (2gh, 2gw)
    const float* base = hqkv + (long)b * 4096 * 768;
#pragma unroll
    for (int it = 0; it < 6; ++it) {
        int idx = tid + it * 128;             // 0..767 float4 units
        int n = idx / 192, c4 = idx % 192;
        int t = t00 + ((n >> 1) << 6) + (n & 1);
        *(float4*)&sq[n][c4 * 4] = *(const float4*)(base + (long)t * 768 + c4 * 4);
    }
    __syncthreads();

    int head = tid >> 5, lane = tid & 31;
    int n = (lane >> 2) & 3, m = lane & 3;
    const float* qn = &sq[n][head * 64];
    const float* km = &sq[m][256 + head * 64];
    float s = 0.f;
#pragma unroll
    for (int k = 0; k < 64; ++k) s += qn[k] * km[k];
    s *= 0.125f;

    float mx = fmaxf(s, __shfl_xor_sync(0xffffffffu, s, 1));
    mx = fmaxf(mx, __shfl_xor_sync(0xffffffffu, mx, 2));
    float p = __expf(s - mx);
    float sum = p;
    sum += __shfl_xor_sync(0xffffffffu, sum, 1);
    sum += __shfl_xor_sync(0xffffffffu, sum, 2);
    p = p / sum;

    int no = lane >> 3;
    int d0 = (lane & 7) << 3;
    float o[8];
#pragma unroll
    for (int dd = 0; dd < 8; ++dd) o[dd] = 0.f;
#pragma unroll
    for (int mm = 0; mm < 4; ++mm) {
        float pm = __shfl_sync(0xffffffffu, p, no * 4 + mm);
        const float* vm = &sq[mm][512 + head * 64 + d0];
#pragma unroll
        for (int dd = 0; dd < 8; ++dd) o[dd] += pm * vm[dd];
    }
    int t = t00 + ((no >> 1) << 6) + (no & 1);
    float* ob = houtT + ((long)(b * 256 + head * 64 + d0)) * 4096 + t;
#pragma unroll
    for (int dd = 0; dd < 8; ++dd) ob[(long)dd * 4096] = o[dd];
}

// ---------------------------------------------------------------------------
// Lo-fi flash attention: CTA = 64 queries x one (b,head); 16 chunks of 64 keys.
// smem: Qs[r][d] (natural), KP (K d-major with xor swizzle, reused for P
// j-major with xor swizzle), Vs[j][d] (natural). 48 KB total.
// Softmax state (m,l) replicated across the 16 tx threads of a row group.
// Output written channel-major (loT: B x 256 x 4096) for the l_proj GEMM.
// ---------------------------------------------------------------------------
__global__ __launch_bounds__(256)
void lofi_flash(const float* __restrict__ lq, const float* __restrict__ lkv,
                float* __restrict__ loT) {
    __shared__ float Qs[4096];
    __shared__ float KP[4096];
    __shared__ float Vs[4096];
    int tid = threadIdx.x;
    int tx = tid & 15, ty = tid >> 4;
    int qb = blockIdx.x, head = blockIdx.y, b = blockIdx.z;
    int t0 = qb << 6;

    const float* lqb = lq + ((long)(b * 4096 + t0)) * 256 + head * 64;
#pragma unroll
    for (int it = 0; it < 4; ++it) {
        int idx = tid + it * 256;
        int t = idx >> 4, d4 = idx & 15;
        float4 v = *(const float4*)(lqb + t * 256 + d4 * 4);
        v.x *= 0.125f; v.y *= 0.125f; v.z *= 0.125f; v.w *= 0.125f;
        *(float4*)&Qs[t * 64 + d4 * 4] = v;
    }

    float acc[4][4], m_i[4], l_i[4];
#pragma unroll
    for (int i = 0; i < 4; i++) {
        m_i[i] = -1e30f; l_i[i] = 0.f;
#pragma unroll
        for (int j = 0; j < 4; j++) acc[i][j] = 0.f;
    }

    const float* kvb = lkv + (long)b * 1024 * 512 + head * 64;

    for (int ch = 0; ch < 16; ++ch) {
        __syncthreads();   // prior-chunk KP/Vs reads done (covers Q load on ch=0)
#pragma unroll
        for (int it = 0; it < 4; ++it) {
            int idx = tid + it * 256;
            int j = idx >> 4, d4 = idx & 15;
            const float* row = kvb + (long)((ch << 6) + j) * 512;
            float4 kv4 = *(const float4*)(row + d4 * 4);
            int sl = (((j >> 2) ^ d4) & 15) << 2;
            int jo = j & 3;
            KP[(d4 * 4 + 0) * 64 + sl + jo] = kv4.x;
            KP[(d4 * 4 + 1) * 64 + sl + jo] = kv4.y;
            KP[(d4 * 4 + 2) * 64 + sl + jo] = kv4.z;
            KP[(d4 * 4 + 3) * 64 + sl + jo] = kv4.w;
            *(float4*)&Vs[j * 64 + d4 * 4] = *(const float4*)(row + 256 + d4 * 4);
        }
        __syncthreads();

        // S = Q * K^T (scale folded into Q)
        float s[4][4];
#pragma unroll
        for (int i = 0; i < 4; i++)
#pragma unroll
            for (int j = 0; j < 4; j++) s[i][j] = 0.f;
#pragma unroll 4
        for (int k = 0; k < 64; ++k) {
            float4 bv = *(float4*)&KP[k * 64 + (((tx ^ (k >> 2)) & 15) << 2)];
#pragma unroll
            for (int i = 0; i < 4; i++) {
                float a = Qs[(ty * 4 + i) * 64 + k];
                s[i][0] += a * bv.x; s[i][1] += a * bv.y;
                s[i][2] += a * bv.z; s[i][3] += a * bv.w;
            }
        }

        // online softmax (reduction across the 16 tx lanes of each row group)
#pragma unroll
        for (int i = 0; i < 4; i++) {
            float mx = fmaxf(fmaxf(s[i][0], s[i][1]), fmaxf(s[i][2], s[i][3]));
            mx = fmaxf(mx, __shfl_xor_sync(0xffffffffu, mx, 1));
            mx = fmaxf(mx, __shfl_xor_sync(0xffffffffu, mx, 2));
            mx = fmaxf(mx, __shfl_xor_sync(0xffffffffu, mx, 4));
            mx = fmaxf(mx, __shfl_xor_sync(0xffffffffu, mx, 8));
            float mnew = fmaxf(m_i[i], mx);
            float alpha = __expf(m_i[i] - mnew);
            float sum = 0.f;
#pragma unroll
            for (int j = 0; j < 4; j++) {
                s[i][j] = __expf(s[i][j] - mnew);
                sum += s[i][j];
            }
            sum += __shfl_xor_sync(0xffffffffu, sum, 1);
            sum += __shfl_xor_sync(0xffffffffu, sum, 2);
            sum += __shfl_xor_sync(0xffffffffu, sum, 4);
            sum += __shfl_xor_sync(0xffffffffu, sum, 8);
            l_i[i] = l_i[i] * alpha + sum;
            m_i[i] = mnew;
#pragma unroll
            for (int j = 0; j < 4; j++) acc[i][j] *= alpha;
        }

        __syncthreads();   // all KP (K) reads done before P overwrites it
        int sl = ((ty ^ tx) & 15) << 2;
#pragma unroll
        for (int jj = 0; jj < 4; jj++)
#pragma unroll
            for (int i = 0; i < 4; i++)
                KP[(tx * 4 + jj) * 64 + sl + i] = s[i][jj];
        __syncthreads();

        // O += P * V
#pragma unroll 4
        for (int j = 0; j < 64; ++j) {
            float4 bv = *(float4*)&Vs[j * 64 + (tx << 2)];
            int so = j * 64 + (((ty ^ (j >> 2)) & 15) << 2);
#pragma unroll
            for (int i = 0; i < 4; i++) {
                float a = KP[so + i];
                acc[i][0] += a * bv.x; acc[i][1] += a * bv.y;
                acc[i][2] += a * bv.z; acc[i][3] += a * bv.w;
            }
        }
    }

    float* outb = loT + ((long)(b * 256 + head * 64 + tx * 4)) * 4096 + t0;
#pragma unroll
    for (int i = 0; i < 4; i++) {
        float inv = __frcp_rn(l_i[i]);
#pragma unroll
        for (int dd = 0; dd < 4; dd++)
            outb[(long)dd * 4096 + ty * 4 + i] = acc[i][dd] * inv;
    }
}

// ---------------------------------------------------------------------------
extern "C" void kernel_launch(void* const* d_in, const int* in_sizes, int n_in,
                              void* d_out, int out_size) {
    const float* x        = (const float*)d_in[0];
    const float* h_qkv_w  = (const float*)d_in[1];
    const float* h_proj_w = (const float*)d_in[2];
    const float* h_proj_b = (const float*)d_in[3];
    const float* l_q_w    = (const float*)d_in[4];
    const float* l_kv_w   = (const float*)d_in[5];
    const float* l_proj_w = (const float*)d_in[6];
    const float* l_proj_b = (const float*)d_in[7];
    float* out = (float*)d_out;

    float* scratch = nullptr;
    cudaGetSymbolAddress((void**)&scratch, g_scratch);
    float* pooledT = scratch + OFF_POOL;
    float* hqkv    = scratch + OFF_HQKV;
    float* lqv     = scratch + OFF_LQ;
    float* lkv     = scratch + OFF_LKV;
    float* houtT   = scratch + OFF_HOUT;
    float* loT     = scratch + OFF_LOT;

    // pooled (B,512,1024) channel-major = A^T for l_kv GEMM
    pool_kernel<<<8192, 256>>>(x, pooledT);

    // hqkv (B,4096,768) = x^T @ h_qkv_w
    sgemm_tn<0, 0><<<dim3(32, 6, NBATCH), 256>>>(
        x, 2097152L, 4096, h_qkv_w, 768, hqkv, 4096L * 768, 768, 0, nullptr, 512);
    // lq (B,4096,256) = x^T @ l_q_w
    sgemm_tn<0, 0><<<dim3(32, 2, NBATCH), 256>>>(
        x, 2097152L, 4096, l_q_w, 256, lqv, 4096L * 256, 256, 0, nullptr, 512);
    // lkv (B,1024,512) = pooled^T @ l_kv_w
    sgemm_tn<0, 0><<<dim3(8, 4, NBATCH), 256>>>(
        pooledT, 524288L, 1024, l_kv_w, 512, lkv, 1024L * 512, 512, 0, nullptr, 512);

    hifi_attn<<<dim3(1024, NBATCH), 128>>>(hqkv, houtT);
    lofi_flash<<<dim3(64, 4, NBATCH), 256>>>(lqv, lkv, loT);

    // out[:, 0:256]  = (houtT^T @ h_proj_w + b), written NCHW channel-major
    sgemm_tn<1, 1><<<dim3(32, 2, NBATCH), 256>>>(
        houtT, 1048576L, 4096, h_proj_w, 256, out, 2097152L, 4096, 0, h_proj_b, 256);
    // out[:, 256:512] = (loT^T @ l_proj_w + b)
    sgemm_tn<1, 1><<<dim3(32, 2, NBATCH), 256>>>(
        loT, 1048576L, 4096, l_proj_w, 256, out, 2097152L, 4096, 256, l_proj_b, 256);
}